// round 1
// baseline (speedup 1.0000x reference)
#include <cuda_runtime.h>
#include <math.h>

#define BATCH  2
#define SEQ    2048
#define DMODEL 2048
#define NHEAD  16
#define DKH    128
#define MTOT   (BATCH*SEQ)

// Scratch in device globals (runtime allocation is forbidden).
__device__ float g_Q[(size_t)BATCH*NHEAD*SEQ*DKH];   // [b][h][s][dk]
__device__ float g_K[(size_t)BATCH*NHEAD*SEQ*DKH];
__device__ float g_V[(size_t)BATCH*NHEAD*SEQ*DKH];
__device__ float g_AO[(size_t)BATCH*SEQ*DMODEL];     // [b][s][h*dk]

// ---------------------------------------------------------------------------
// C[m,e] = sum_d A[m,d] * W[e,d]   (A: [M,2048] row-major, W: [2048,2048])
// MODE 0: write head layout [b][h][s][dk], no RoPE     (V projection)
// MODE 1: write head layout with RoPE applied          (Q, K projections)
// MODE 2: write row-major [m][e]                       (output projection)
// Tile: 128x128x8, 256 threads, 8x8 accumulators per thread.
// ---------------------------------------------------------------------------
template<int MODE>
__global__ void __launch_bounds__(256)
gemm_proj(const float* __restrict__ A, const float* __restrict__ W,
          const int* __restrict__ pos, float* __restrict__ out)
{
    __shared__ float As[8][132];   // [k][m], padded stride
    __shared__ float Bs[8][132];   // [k][n]

    const int bm  = blockIdx.y * 128;
    const int bn  = blockIdx.x * 128;
    const int tid = threadIdx.x;
    const int tr  = tid >> 4;          // 0..15
    const int tc  = tid & 15;          // 0..15
    const int lrow = tid >> 1;         // 0..127
    const int lcol = (tid & 1) << 2;   // 0 or 4

    const float* Ap = A + (size_t)(bm + lrow) * DMODEL + lcol;
    const float* Wp = W + (size_t)(bn + lrow) * DMODEL + lcol;

    float acc[8][8];
    #pragma unroll
    for (int i = 0; i < 8; i++)
        #pragma unroll
        for (int j = 0; j < 8; j++) acc[i][j] = 0.f;

    for (int k0 = 0; k0 < DMODEL; k0 += 8) {
        const float4 av = *(const float4*)(Ap + k0);
        const float4 wv = *(const float4*)(Wp + k0);
        As[lcol+0][lrow] = av.x; As[lcol+1][lrow] = av.y;
        As[lcol+2][lrow] = av.z; As[lcol+3][lrow] = av.w;
        Bs[lcol+0][lrow] = wv.x; Bs[lcol+1][lrow] = wv.y;
        Bs[lcol+2][lrow] = wv.z; Bs[lcol+3][lrow] = wv.w;
        __syncthreads();
        #pragma unroll
        for (int k = 0; k < 8; k++) {
            float ar[8], br[8];
            *(float4*)(ar)     = *(const float4*)(&As[k][tr*8]);
            *(float4*)(ar + 4) = *(const float4*)(&As[k][tr*8 + 4]);
            *(float4*)(br)     = *(const float4*)(&Bs[k][tc*8]);
            *(float4*)(br + 4) = *(const float4*)(&Bs[k][tc*8 + 4]);
            #pragma unroll
            for (int i = 0; i < 8; i++)
                #pragma unroll
                for (int j = 0; j < 8; j++)
                    acc[i][j] = fmaf(ar[i], br[j], acc[i][j]);
        }
        __syncthreads();
    }

    const int row0 = bm + tr*8;
    const int col0 = bn + tc*8;

    if (MODE == 2) {
        #pragma unroll
        for (int i = 0; i < 8; i++) {
            float* op = out + (size_t)(row0 + i) * DMODEL + col0;
            *(float4*)op       = make_float4(acc[i][0], acc[i][1], acc[i][2], acc[i][3]);
            *(float4*)(op + 4) = make_float4(acc[i][4], acc[i][5], acc[i][6], acc[i][7]);
        }
    } else {
        const int hh = col0 >> 7;     // head
        const int jh = col0 & 127;    // offset within head (even, multiple of 8)
        float freqs[4];
        if (MODE == 1) {
            #pragma unroll
            for (int t = 0; t < 4; t++)
                // theta^(-(2p)/dk); 2p = jh+2t. ln(10000)=9.210340371976184
                freqs[t] = (float)exp(-(double)(jh + 2*t) * (9.210340371976184 / 128.0));
        }
        #pragma unroll
        for (int i = 0; i < 8; i++) {
            const int gm = row0 + i;
            const int bb = gm >> 11;       // / SEQ
            const int ss = gm & (SEQ - 1);
            float v[8];
            #pragma unroll
            for (int j = 0; j < 8; j++) v[j] = acc[i][j];
            if (MODE == 1) {
                const float p = (float)pos[gm];
                #pragma unroll
                for (int t = 0; t < 4; t++) {
                    float sn, cs;
                    sincosf(p * freqs[t], &sn, &cs);
                    const float ev = v[2*t], od = v[2*t+1];
                    v[2*t]   = ev*cs - od*sn;
                    v[2*t+1] = ev*sn + od*cs;
                }
            }
            float* op = out + ((size_t)(bb*NHEAD + hh)*SEQ + ss)*DKH + jh;
            *(float4*)op       = make_float4(v[0], v[1], v[2], v[3]);
            *(float4*)(op + 4) = make_float4(v[4], v[5], v[6], v[7]);
        }
    }
}

// ---------------------------------------------------------------------------
// Causal flash attention, fp32. One CTA per (b, h, 64-query tile).
// Q/K staged d-major (stride 65) in smem; V row-major; online softmax with
// 4-lanes-per-row shuffle reductions. O accumulators in registers.
// ---------------------------------------------------------------------------
__global__ void __launch_bounds__(256)
attn_kernel(const float* __restrict__ Q, const float* __restrict__ K,
            const float* __restrict__ V, float* __restrict__ Out)
{
    extern __shared__ float sm[];
    float* QT = sm;                  // [128][65]  QT[d*65 + r]
    float* KT = sm + 128*65;         // [128][65]
    float* VS = KT + 128*65;         // [64][128]  row-major
    float* PS = VS + 64*128;         // [64][65]

    const int qt = blockIdx.x;
    const int h  = blockIdx.y;
    const int b  = blockIdx.z;
    const int q0 = qt * 64;
    const int tid = threadIdx.x;

    const size_t base = ((size_t)(b*NHEAD + h)) * SEQ * DKH;

    // Load Q tile (contiguous 8192 floats), store transposed.
    {
        const float4* Qg = (const float4*)(Q + base + (size_t)q0 * DKH);
        #pragma unroll
        for (int i = 0; i < 8; i++) {
            const int f4 = tid + i*256;
            const int r  = f4 >> 5;
            const int dc = (f4 & 31) << 2;
            const float4 v = Qg[f4];
            QT[(dc+0)*65 + r] = v.x; QT[(dc+1)*65 + r] = v.y;
            QT[(dc+2)*65 + r] = v.z; QT[(dc+3)*65 + r] = v.w;
        }
    }

    const int tr = tid >> 4, tc = tid & 15;     // S-compute mapping
    const int r0 = tr*4,     c0 = tc*4;
    const int orow = tid >> 2, oq = tid & 3;    // softmax / O mapping

    float4 o4[8];
    #pragma unroll
    for (int i = 0; i < 8; i++) o4[i] = make_float4(0.f, 0.f, 0.f, 0.f);
    float m = -1e30f, l = 0.f;
    const float scale = 0.08838834764831845f;   // 1/sqrt(128)

    const int ntiles = qt + 1;
    for (int kt = 0; kt < ntiles; kt++) {
        const int k0 = kt * 64;
        __syncthreads();   // previous iteration done reading KT/VS/PS

        // Load K (transposed) and V (row-major) tiles.
        {
            const float4* Kg = (const float4*)(K + base + (size_t)k0 * DKH);
            const float4* Vg = (const float4*)(V + base + (size_t)k0 * DKH);
            float4* VS4 = (float4*)VS;
            #pragma unroll
            for (int i = 0; i < 8; i++) {
                const int f4 = tid + i*256;
                const int r  = f4 >> 5;
                const int dc = (f4 & 31) << 2;
                const float4 kv = Kg[f4];
                KT[(dc+0)*65 + r] = kv.x; KT[(dc+1)*65 + r] = kv.y;
                KT[(dc+2)*65 + r] = kv.z; KT[(dc+3)*65 + r] = kv.w;
                VS4[f4] = Vg[f4];
            }
        }
        __syncthreads();

        // S = Q K^T (4x4 per thread over 64x64 tile)
        float sacc[4][4];
        #pragma unroll
        for (int i = 0; i < 4; i++)
            #pragma unroll
            for (int t = 0; t < 4; t++) sacc[i][t] = 0.f;

        #pragma unroll 8
        for (int d = 0; d < 128; d++) {
            float qv[4], kv[4];
            #pragma unroll
            for (int i = 0; i < 4; i++) qv[i] = QT[d*65 + r0 + i];
            #pragma unroll
            for (int t = 0; t < 4; t++) kv[t] = KT[d*65 + c0 + t];
            #pragma unroll
            for (int i = 0; i < 4; i++)
                #pragma unroll
                for (int t = 0; t < 4; t++)
                    sacc[i][t] = fmaf(qv[i], kv[t], sacc[i][t]);
        }

        const bool diag = (kt == qt);
        #pragma unroll
        for (int i = 0; i < 4; i++)
            #pragma unroll
            for (int t = 0; t < 4; t++) {
                float v = sacc[i][t] * scale;
                if (diag && (k0 + c0 + t) > (q0 + r0 + i)) v = -1e30f;
                PS[(r0 + i)*65 + c0 + t] = v;
            }
        __syncthreads();

        // Online softmax: row = orow, 4 lanes per row, 16 cols each.
        float mloc = -1e30f;
        #pragma unroll
        for (int c = 0; c < 16; c++)
            mloc = fmaxf(mloc, PS[orow*65 + oq*16 + c]);
        mloc = fmaxf(mloc, __shfl_xor_sync(0xffffffffu, mloc, 1));
        mloc = fmaxf(mloc, __shfl_xor_sync(0xffffffffu, mloc, 2));
        const float mnew = fmaxf(m, mloc);
        const float corr = __expf(m - mnew);
        float ssum = 0.f;
        #pragma unroll
        for (int c = 0; c < 16; c++) {
            const int idx = orow*65 + oq*16 + c;
            const float p = __expf(PS[idx] - mnew);
            PS[idx] = p;
            ssum += p;
        }
        ssum += __shfl_xor_sync(0xffffffffu, ssum, 1);
        ssum += __shfl_xor_sync(0xffffffffu, ssum, 2);
        l = l * corr + ssum;
        m = mnew;
        #pragma unroll
        for (int i = 0; i < 8; i++) {
            o4[i].x *= corr; o4[i].y *= corr; o4[i].z *= corr; o4[i].w *= corr;
        }
        __syncwarp();   // PS row writes are warp-local per row

        // O += P V
        const float4* VS4 = (const float4*)VS;
        #pragma unroll 4
        for (int j = 0; j < 64; j++) {
            const float p = PS[orow*65 + j];
            #pragma unroll
            for (int i = 0; i < 8; i++) {
                const float4 v = VS4[j*32 + oq + 4*i];
                o4[i].x = fmaf(p, v.x, o4[i].x);
                o4[i].y = fmaf(p, v.y, o4[i].y);
                o4[i].z = fmaf(p, v.z, o4[i].z);
                o4[i].w = fmaf(p, v.w, o4[i].w);
            }
        }
    }

    // Normalize and write to [b][s][h*dk + d]
    const float inv = 1.f / l;
    float* op = Out + ((size_t)(b*SEQ + q0 + orow))*DMODEL + h*DKH;
    #pragma unroll
    for (int i = 0; i < 8; i++) {
        float4 v = o4[i];
        v.x *= inv; v.y *= inv; v.z *= inv; v.w *= inv;
        *(float4*)(op + 4*(oq + 4*i)) = v;
    }
}

// ---------------------------------------------------------------------------
extern "C" void kernel_launch(void* const* d_in, const int* in_sizes, int n_in,
                              void* d_out, int out_size)
{
    (void)in_sizes; (void)n_in; (void)out_size;
    const float* x  = (const float*)d_in[0];
    const int*   tp = (const int*)  d_in[1];
    const float* wq = (const float*)d_in[2];
    const float* wk = (const float*)d_in[3];
    const float* wv = (const float*)d_in[4];
    const float* wo = (const float*)d_in[5];
    float* out = (float*)d_out;

    float *Qp, *Kp, *Vp, *AOp;
    cudaGetSymbolAddress((void**)&Qp,  g_Q);
    cudaGetSymbolAddress((void**)&Kp,  g_K);
    cudaGetSymbolAddress((void**)&Vp,  g_V);
    cudaGetSymbolAddress((void**)&AOp, g_AO);

    const dim3 gg(DMODEL/128, MTOT/128);
    gemm_proj<1><<<gg, 256>>>(x, wq, tp, Qp);
    gemm_proj<1><<<gg, 256>>>(x, wk, tp, Kp);
    gemm_proj<0><<<gg, 256>>>(x, wv, tp, Vp);

    const int smem = (128*65*2 + 64*128 + 64*65) * (int)sizeof(float);
    cudaFuncSetAttribute(attn_kernel,
                         cudaFuncAttributeMaxDynamicSharedMemorySize, smem);
    attn_kernel<<<dim3(SEQ/64, NHEAD, BATCH), 256, smem>>>(Qp, Kp, Vp, AOp);

    gemm_proj<2><<<gg, 256>>>(AOp, wo, tp, out);
}

// round 2
// speedup vs baseline: 1.9174x; 1.9174x over previous
#include <cuda_runtime.h>
#include <math.h>
#include <stdint.h>

#define BATCH  2
#define SEQ    2048
#define DMODEL 2048
#define NHEAD  16
#define DKH    128
#define MTOT   (BATCH*SEQ)

// Scratch in device globals (runtime allocation is forbidden).
__device__ float g_Q[(size_t)BATCH*NHEAD*SEQ*DKH];   // [b][h][s][dk]
__device__ float g_K[(size_t)BATCH*NHEAD*SEQ*DKH];
__device__ float g_V[(size_t)BATCH*NHEAD*SEQ*DKH];
__device__ float g_AO[(size_t)BATCH*SEQ*DMODEL];     // [b][s][h*dk]

// ---------------------------------------------------------------------------
// TF32 tensor-core GEMM:  C[m,e] = sum_d A[m,d] * W[e,d]
//   A: [M,2048] row-major, W: [2048,2048] row-major ("col" operand for mma)
// MODE 0: write head layout [b][h][s][dk], no RoPE     (V projection)
// MODE 1: write head layout with RoPE applied          (Q, K projections)
// MODE 2: write row-major [m][e]                       (output projection)
// CTA tile 128x128x32, 256 threads = 8 warps, warp tile 64x32.
// mma.sync.aligned.m16n8k8.row.col.f32.tf32.tf32.f32
// ---------------------------------------------------------------------------
__device__ __forceinline__ uint32_t f2tf32(float x) {
    uint32_t r;
    asm("cvt.rna.tf32.f32 %0, %1;" : "=r"(r) : "f"(x));
    return r;
}

__device__ __forceinline__ void mma_tf32(float* d, const uint32_t* a, const uint32_t* b) {
    asm volatile(
        "mma.sync.aligned.m16n8k8.row.col.f32.tf32.tf32.f32 "
        "{%0,%1,%2,%3}, {%4,%5,%6,%7}, {%8,%9}, {%0,%1,%2,%3};\n"
        : "+f"(d[0]), "+f"(d[1]), "+f"(d[2]), "+f"(d[3])
        : "r"(a[0]), "r"(a[1]), "r"(a[2]), "r"(a[3]),
          "r"(b[0]), "r"(b[1]));
}

#define SMS 36   // smem row stride (floats): conflict-free fragment reads

template<int MODE>
__global__ void __launch_bounds__(256)
gemm_tc(const float* __restrict__ A, const float* __restrict__ W,
        const int* __restrict__ pos, float* __restrict__ out)
{
    __shared__ uint32_t As[128*SMS];
    __shared__ uint32_t Bs[128*SMS];

    const int bm = blockIdx.y * 128;
    const int bn = blockIdx.x * 128;
    const int tid  = threadIdx.x;
    const int warp = tid >> 5;
    const int lane = tid & 31;
    const int wm = (warp & 1) * 64;    // warp M offset
    const int wn = (warp >> 1) * 32;   // warp N offset
    const int grp = lane >> 2;         // 0..7
    const int tg  = lane & 3;          // 0..3

    // Global-load mapping: 32 rows x 32 k per pass, 4 passes.
    const int lr = tid >> 3;           // 0..31
    const int lc = (tid & 7) * 4;      // 0,4,...,28

    const float* Ap = A + (size_t)(bm + lr) * DMODEL + lc;
    const float* Wp = W + (size_t)(bn + lr) * DMODEL + lc;

    float acc[4][4][4];
    #pragma unroll
    for (int mi = 0; mi < 4; mi++)
        #pragma unroll
        for (int ni = 0; ni < 4; ni++)
            #pragma unroll
            for (int r = 0; r < 4; r++) acc[mi][ni][r] = 0.f;

    float4 pa[4], pw[4];
    #pragma unroll
    for (int p = 0; p < 4; p++) {
        pa[p] = *(const float4*)(Ap + (size_t)p*32*DMODEL);
        pw[p] = *(const float4*)(Wp + (size_t)p*32*DMODEL);
    }

    for (int k0 = 0; k0 < DMODEL; k0 += 32) {
        __syncthreads();
        #pragma unroll
        for (int p = 0; p < 4; p++) {
            uint32_t* as = &As[(lr + p*32)*SMS + lc];
            uint32_t* bs = &Bs[(lr + p*32)*SMS + lc];
            as[0] = f2tf32(pa[p].x); as[1] = f2tf32(pa[p].y);
            as[2] = f2tf32(pa[p].z); as[3] = f2tf32(pa[p].w);
            bs[0] = f2tf32(pw[p].x); bs[1] = f2tf32(pw[p].y);
            bs[2] = f2tf32(pw[p].z); bs[3] = f2tf32(pw[p].w);
        }
        __syncthreads();

        if (k0 + 32 < DMODEL) {
            #pragma unroll
            for (int p = 0; p < 4; p++) {
                pa[p] = *(const float4*)(Ap + (size_t)p*32*DMODEL + k0 + 32);
                pw[p] = *(const float4*)(Wp + (size_t)p*32*DMODEL + k0 + 32);
            }
        }

        #pragma unroll
        for (int ks = 0; ks < 32; ks += 8) {
            uint32_t a[4][4], b[4][2];
            #pragma unroll
            for (int mi = 0; mi < 4; mi++) {
                const int m0 = wm + mi*16 + grp;
                a[mi][0] = As[(m0    )*SMS + ks     + tg];
                a[mi][1] = As[(m0 + 8)*SMS + ks     + tg];
                a[mi][2] = As[(m0    )*SMS + ks + 4 + tg];
                a[mi][3] = As[(m0 + 8)*SMS + ks + 4 + tg];
            }
            #pragma unroll
            for (int ni = 0; ni < 4; ni++) {
                const int n0 = wn + ni*8 + grp;
                b[ni][0] = Bs[n0*SMS + ks     + tg];
                b[ni][1] = Bs[n0*SMS + ks + 4 + tg];
            }
            #pragma unroll
            for (int mi = 0; mi < 4; mi++)
                #pragma unroll
                for (int ni = 0; ni < 4; ni++)
                    mma_tf32(acc[mi][ni], a[mi], b[ni]);
        }
    }

    // ---------------- epilogue ----------------
    if (MODE == 2) {
        #pragma unroll
        for (int mi = 0; mi < 4; mi++) {
            const int r0 = bm + wm + mi*16 + grp;
            #pragma unroll
            for (int half = 0; half < 2; half++) {
                const int gm = r0 + half*8;
                #pragma unroll
                for (int ni = 0; ni < 4; ni++) {
                    const int col = bn + wn + ni*8 + tg*2;
                    float2 v = make_float2(acc[mi][ni][half*2], acc[mi][ni][half*2+1]);
                    *(float2*)(out + (size_t)gm * DMODEL + col) = v;
                }
            }
        }
    } else {
        float freq[4];
        if (MODE == 1) {
            #pragma unroll
            for (int ni = 0; ni < 4; ni++) {
                const int jh = (wn + ni*8 + tg*2) & 127;
                freq[ni] = (float)exp(-(double)jh * (9.210340371976184 / 128.0));
            }
        }
        #pragma unroll
        for (int mi = 0; mi < 4; mi++) {
            #pragma unroll
            for (int half = 0; half < 2; half++) {
                const int gm = bm + wm + mi*16 + grp + half*8;
                const int bb = gm >> 11;
                const int ss = gm & (SEQ - 1);
                float p = 0.f;
                if (MODE == 1) p = (float)pos[gm];
                #pragma unroll
                for (int ni = 0; ni < 4; ni++) {
                    const int col = bn + wn + ni*8 + tg*2;
                    const int hh = col >> 7;
                    const int jh = col & 127;
                    float e = acc[mi][ni][half*2], o = acc[mi][ni][half*2+1];
                    if (MODE == 1) {
                        float sn, cs;
                        sincosf(p * freq[ni], &sn, &cs);
                        const float te = e*cs - o*sn;
                        o = e*sn + o*cs;
                        e = te;
                    }
                    *(float2*)(out + ((size_t)(bb*NHEAD + hh)*SEQ + ss)*DKH + jh)
                        = make_float2(e, o);
                }
            }
        }
    }
}

// ---------------------------------------------------------------------------
// Causal flash attention, fp32 (unchanged from passing R1 kernel).
// ---------------------------------------------------------------------------
__global__ void __launch_bounds__(256)
attn_kernel(const float* __restrict__ Q, const float* __restrict__ K,
            const float* __restrict__ V, float* __restrict__ Out)
{
    extern __shared__ float sm[];
    float* QT = sm;                  // [128][65]  QT[d*65 + r]
    float* KT = sm + 128*65;         // [128][65]
    float* VS = KT + 128*65;         // [64][128]  row-major
    float* PS = VS + 64*128;         // [64][65]

    const int qt = blockIdx.x;
    const int h  = blockIdx.y;
    const int b  = blockIdx.z;
    const int q0 = qt * 64;
    const int tid = threadIdx.x;

    const size_t base = ((size_t)(b*NHEAD + h)) * SEQ * DKH;

    {
        const float4* Qg = (const float4*)(Q + base + (size_t)q0 * DKH);
        #pragma unroll
        for (int i = 0; i < 8; i++) {
            const int f4 = tid + i*256;
            const int r  = f4 >> 5;
            const int dc = (f4 & 31) << 2;
            const float4 v = Qg[f4];
            QT[(dc+0)*65 + r] = v.x; QT[(dc+1)*65 + r] = v.y;
            QT[(dc+2)*65 + r] = v.z; QT[(dc+3)*65 + r] = v.w;
        }
    }

    const int tr = tid >> 4, tc = tid & 15;
    const int r0 = tr*4,     c0 = tc*4;
    const int orow = tid >> 2, oq = tid & 3;

    float4 o4[8];
    #pragma unroll
    for (int i = 0; i < 8; i++) o4[i] = make_float4(0.f, 0.f, 0.f, 0.f);
    float m = -1e30f, l = 0.f;
    const float scale = 0.08838834764831845f;

    const int ntiles = qt + 1;
    for (int kt = 0; kt < ntiles; kt++) {
        const int k0 = kt * 64;
        __syncthreads();

        {
            const float4* Kg = (const float4*)(K + base + (size_t)k0 * DKH);
            const float4* Vg = (const float4*)(V + base + (size_t)k0 * DKH);
            float4* VS4 = (float4*)VS;
            #pragma unroll
            for (int i = 0; i < 8; i++) {
                const int f4 = tid + i*256;
                const int r  = f4 >> 5;
                const int dc = (f4 & 31) << 2;
                const float4 kv = Kg[f4];
                KT[(dc+0)*65 + r] = kv.x; KT[(dc+1)*65 + r] = kv.y;
                KT[(dc+2)*65 + r] = kv.z; KT[(dc+3)*65 + r] = kv.w;
                VS4[f4] = Vg[f4];
            }
        }
        __syncthreads();

        float sacc[4][4];
        #pragma unroll
        for (int i = 0; i < 4; i++)
            #pragma unroll
            for (int t = 0; t < 4; t++) sacc[i][t] = 0.f;

        #pragma unroll 8
        for (int d = 0; d < 128; d++) {
            float qv[4], kv[4];
            #pragma unroll
            for (int i = 0; i < 4; i++) qv[i] = QT[d*65 + r0 + i];
            #pragma unroll
            for (int t = 0; t < 4; t++) kv[t] = KT[d*65 + c0 + t];
            #pragma unroll
            for (int i = 0; i < 4; i++)
                #pragma unroll
                for (int t = 0; t < 4; t++)
                    sacc[i][t] = fmaf(qv[i], kv[t], sacc[i][t]);
        }

        const bool diag = (kt == qt);
        #pragma unroll
        for (int i = 0; i < 4; i++)
            #pragma unroll
            for (int t = 0; t < 4; t++) {
                float v = sacc[i][t] * scale;
                if (diag && (k0 + c0 + t) > (q0 + r0 + i)) v = -1e30f;
                PS[(r0 + i)*65 + c0 + t] = v;
            }
        __syncthreads();

        float mloc = -1e30f;
        #pragma unroll
        for (int c = 0; c < 16; c++)
            mloc = fmaxf(mloc, PS[orow*65 + oq*16 + c]);
        mloc = fmaxf(mloc, __shfl_xor_sync(0xffffffffu, mloc, 1));
        mloc = fmaxf(mloc, __shfl_xor_sync(0xffffffffu, mloc, 2));
        const float mnew = fmaxf(m, mloc);
        const float corr = __expf(m - mnew);
        float ssum = 0.f;
        #pragma unroll
        for (int c = 0; c < 16; c++) {
            const int idx = orow*65 + oq*16 + c;
            const float p = __expf(PS[idx] - mnew);
            PS[idx] = p;
            ssum += p;
        }
        ssum += __shfl_xor_sync(0xffffffffu, ssum, 1);
        ssum += __shfl_xor_sync(0xffffffffu, ssum, 2);
        l = l * corr + ssum;
        m = mnew;
        #pragma unroll
        for (int i = 0; i < 8; i++) {
            o4[i].x *= corr; o4[i].y *= corr; o4[i].z *= corr; o4[i].w *= corr;
        }
        __syncwarp();

        const float4* VS4 = (const float4*)VS;
        #pragma unroll 4
        for (int j = 0; j < 64; j++) {
            const float p = PS[orow*65 + j];
            #pragma unroll
            for (int i = 0; i < 8; i++) {
                const float4 v = VS4[j*32 + oq + 4*i];
                o4[i].x = fmaf(p, v.x, o4[i].x);
                o4[i].y = fmaf(p, v.y, o4[i].y);
                o4[i].z = fmaf(p, v.z, o4[i].z);
                o4[i].w = fmaf(p, v.w, o4[i].w);
            }
        }
    }

    const float inv = 1.f / l;
    float* op = Out + ((size_t)(b*SEQ + q0 + orow))*DMODEL + h*DKH;
    #pragma unroll
    for (int i = 0; i < 8; i++) {
        float4 v = o4[i];
        v.x *= inv; v.y *= inv; v.z *= inv; v.w *= inv;
        *(float4*)(op + 4*(oq + 4*i)) = v;
    }
}

// ---------------------------------------------------------------------------
extern "C" void kernel_launch(void* const* d_in, const int* in_sizes, int n_in,
                              void* d_out, int out_size)
{
    (void)in_sizes; (void)n_in; (void)out_size;
    const float* x  = (const float*)d_in[0];
    const int*   tp = (const int*)  d_in[1];
    const float* wq = (const float*)d_in[2];
    const float* wk = (const float*)d_in[3];
    const float* wv = (const float*)d_in[4];
    const float* wo = (const float*)d_in[5];
    float* out = (float*)d_out;

    float *Qp, *Kp, *Vp, *AOp;
    cudaGetSymbolAddress((void**)&Qp,  g_Q);
    cudaGetSymbolAddress((void**)&Kp,  g_K);
    cudaGetSymbolAddress((void**)&Vp,  g_V);
    cudaGetSymbolAddress((void**)&AOp, g_AO);

    const dim3 gg(DMODEL/128, MTOT/128);
    gemm_tc<1><<<gg, 256>>>(x, wq, tp, Qp);
    gemm_tc<1><<<gg, 256>>>(x, wk, tp, Kp);
    gemm_tc<0><<<gg, 256>>>(x, wv, tp, Vp);

    const int smem = (128*65*2 + 64*128 + 64*65) * (int)sizeof(float);
    cudaFuncSetAttribute(attn_kernel,
                         cudaFuncAttributeMaxDynamicSharedMemorySize, smem);
    attn_kernel<<<dim3(SEQ/64, NHEAD, BATCH), 256, smem>>>(Qp, Kp, Vp, AOp);

    gemm_tc<2><<<gg, 256>>>(AOp, wo, tp, out);
}

// round 4
// speedup vs baseline: 3.7369x; 1.9490x over previous
#include <cuda_runtime.h>
#include <math.h>
#include <stdint.h>

#define BATCH  2
#define SEQ    2048
#define DMODEL 2048
#define NHEAD  16
#define DKH    128
#define MTOT   (BATCH*SEQ)

__device__ float g_Q[(size_t)BATCH*NHEAD*SEQ*DKH];   // [b][h][s][dk]
__device__ float g_K[(size_t)BATCH*NHEAD*SEQ*DKH];
__device__ float g_V[(size_t)BATCH*NHEAD*SEQ*DKH];
__device__ float g_AO[(size_t)BATCH*SEQ*DMODEL];     // [b][s][h*dk]

__device__ __forceinline__ uint32_t f2tf32(float x) {
    uint32_t r;
    asm("cvt.rna.tf32.f32 %0, %1;" : "=r"(r) : "f"(x));
    return r;
}

__device__ __forceinline__ void mma_tf32(float* d, const uint32_t* a, const uint32_t* b) {
    asm volatile(
        "mma.sync.aligned.m16n8k8.row.col.f32.tf32.tf32.f32 "
        "{%0,%1,%2,%3}, {%4,%5,%6,%7}, {%8,%9}, {%0,%1,%2,%3};\n"
        : "+f"(d[0]), "+f"(d[1]), "+f"(d[2]), "+f"(d[3])
        : "r"(a[0]), "r"(a[1]), "r"(a[2]), "r"(a[3]),
          "r"(b[0]), "r"(b[1]));
}

// ---------------------------------------------------------------------------
// TF32 tensor-core GEMM (unchanged from passing R2 kernel).
// ---------------------------------------------------------------------------
#define SMS 36

template<int MODE>
__global__ void __launch_bounds__(256)
gemm_tc(const float* __restrict__ A, const float* __restrict__ W,
        const int* __restrict__ pos, float* __restrict__ out)
{
    __shared__ uint32_t As[128*SMS];
    __shared__ uint32_t Bs[128*SMS];

    const int bm = blockIdx.y * 128;
    const int bn = blockIdx.x * 128;
    const int tid  = threadIdx.x;
    const int warp = tid >> 5;
    const int lane = tid & 31;
    const int wm = (warp & 1) * 64;
    const int wn = (warp >> 1) * 32;
    const int grp = lane >> 2;
    const int tg  = lane & 3;

    const int lr = tid >> 3;
    const int lc = (tid & 7) * 4;

    const float* Ap = A + (size_t)(bm + lr) * DMODEL + lc;
    const float* Wp = W + (size_t)(bn + lr) * DMODEL + lc;

    float acc[4][4][4];
    #pragma unroll
    for (int mi = 0; mi < 4; mi++)
        #pragma unroll
        for (int ni = 0; ni < 4; ni++)
            #pragma unroll
            for (int r = 0; r < 4; r++) acc[mi][ni][r] = 0.f;

    float4 pa[4], pw[4];
    #pragma unroll
    for (int p = 0; p < 4; p++) {
        pa[p] = *(const float4*)(Ap + (size_t)p*32*DMODEL);
        pw[p] = *(const float4*)(Wp + (size_t)p*32*DMODEL);
    }

    for (int k0 = 0; k0 < DMODEL; k0 += 32) {
        __syncthreads();
        #pragma unroll
        for (int p = 0; p < 4; p++) {
            uint32_t* as = &As[(lr + p*32)*SMS + lc];
            uint32_t* bs = &Bs[(lr + p*32)*SMS + lc];
            as[0] = f2tf32(pa[p].x); as[1] = f2tf32(pa[p].y);
            as[2] = f2tf32(pa[p].z); as[3] = f2tf32(pa[p].w);
            bs[0] = f2tf32(pw[p].x); bs[1] = f2tf32(pw[p].y);
            bs[2] = f2tf32(pw[p].z); bs[3] = f2tf32(pw[p].w);
        }
        __syncthreads();

        if (k0 + 32 < DMODEL) {
            #pragma unroll
            for (int p = 0; p < 4; p++) {
                pa[p] = *(const float4*)(Ap + (size_t)p*32*DMODEL + k0 + 32);
                pw[p] = *(const float4*)(Wp + (size_t)p*32*DMODEL + k0 + 32);
            }
        }

        #pragma unroll
        for (int ks = 0; ks < 32; ks += 8) {
            uint32_t a[4][4], b[4][2];
            #pragma unroll
            for (int mi = 0; mi < 4; mi++) {
                const int m0 = wm + mi*16 + grp;
                a[mi][0] = As[(m0    )*SMS + ks     + tg];
                a[mi][1] = As[(m0 + 8)*SMS + ks     + tg];
                a[mi][2] = As[(m0    )*SMS + ks + 4 + tg];
                a[mi][3] = As[(m0 + 8)*SMS + ks + 4 + tg];
            }
            #pragma unroll
            for (int ni = 0; ni < 4; ni++) {
                const int n0 = wn + ni*8 + grp;
                b[ni][0] = Bs[n0*SMS + ks     + tg];
                b[ni][1] = Bs[n0*SMS + ks + 4 + tg];
            }
            #pragma unroll
            for (int mi = 0; mi < 4; mi++)
                #pragma unroll
                for (int ni = 0; ni < 4; ni++)
                    mma_tf32(acc[mi][ni], a[mi], b[ni]);
        }
    }

    if (MODE == 2) {
        #pragma unroll
        for (int mi = 0; mi < 4; mi++) {
            const int r0 = bm + wm + mi*16 + grp;
            #pragma unroll
            for (int half = 0; half < 2; half++) {
                const int gm = r0 + half*8;
                #pragma unroll
                for (int ni = 0; ni < 4; ni++) {
                    const int col = bn + wn + ni*8 + tg*2;
                    float2 v = make_float2(acc[mi][ni][half*2], acc[mi][ni][half*2+1]);
                    *(float2*)(out + (size_t)gm * DMODEL + col) = v;
                }
            }
        }
    } else {
        float freq[4];
        if (MODE == 1) {
            #pragma unroll
            for (int ni = 0; ni < 4; ni++) {
                const int jh = (wn + ni*8 + tg*2) & 127;
                freq[ni] = (float)exp(-(double)jh * (9.210340371976184 / 128.0));
            }
        }
        #pragma unroll
        for (int mi = 0; mi < 4; mi++) {
            #pragma unroll
            for (int half = 0; half < 2; half++) {
                const int gm = bm + wm + mi*16 + grp + half*8;
                const int bb = gm >> 11;
                const int ss = gm & (SEQ - 1);
                float p = 0.f;
                if (MODE == 1) p = (float)pos[gm];
                #pragma unroll
                for (int ni = 0; ni < 4; ni++) {
                    const int col = bn + wn + ni*8 + tg*2;
                    const int hh = col >> 7;
                    const int jh = col & 127;
                    float e = acc[mi][ni][half*2], o = acc[mi][ni][half*2+1];
                    if (MODE == 1) {
                        float sn, cs;
                        sincosf(p * freq[ni], &sn, &cs);
                        const float te = e*cs - o*sn;
                        o = e*sn + o*cs;
                        e = te;
                    }
                    *(float2*)(out + ((size_t)(bb*NHEAD + hh)*SEQ + ss)*DKH + jh)
                        = make_float2(e, o);
                }
            }
        }
    }
}

// ---------------------------------------------------------------------------
// TF32 tensor-core causal flash attention.
// CTA: 64 queries, 4 warps (16 rows each), 64-key tiles, dk = 128.
// Q persistent in registers as mma A-fragments. K/V/P in smem with inner-8
// permutation perm8(r)=((r&3)<<1)|(r>>2) making (k=tg, k=tg+4) fragment pairs
// adjacent -> single LDS.64 per fragment.
//   KS[key][pd(d)]     stride 132   (B operand of S = Q K^T)
//   VS[dk][pk(key)]    stride 70    (B operand of O += P V)
//   PS[q][pd(key)]     stride 70    (A operand of O += P V), tf32 bits
// ---------------------------------------------------------------------------
#define KSS 132
#define VSS 70
#define PSS 70

__device__ __forceinline__ int perm8(int r) { return ((r & 3) << 1) | (r >> 2); }

__global__ void __launch_bounds__(128)
attn_tc(const float* __restrict__ Q, const float* __restrict__ K,
        const float* __restrict__ V, float* __restrict__ Out)
{
    extern __shared__ float sm[];
    float* KS = sm;                       // [64][132]
    float* VS = sm + 64*KSS;              // [128][70]
    float* PS = VS + 128*VSS;             // [64][70]

    const int qt = blockIdx.x;
    const int h  = blockIdx.y;
    const int b  = blockIdx.z;
    const int q0 = qt * 64;
    const int tid  = threadIdx.x;
    const int w    = tid >> 5;
    const int lane = tid & 31;
    const int grp  = lane >> 2;
    const int tg   = lane & 3;

    const size_t base = ((size_t)(b*NHEAD + h)) * SEQ * DKH;

    // ---- persistent Q fragments ----
    const int mlo = q0 + w*16 + grp;       // global row (low half)
    uint32_t qa[16][4];
    {
        const float* Qlo = Q + base + (size_t)mlo * DKH;
        const float* Qhi = Qlo + 8*DKH;
        #pragma unroll
        for (int kk = 0; kk < 16; kk++) {
            qa[kk][0] = f2tf32(Qlo[kk*8 + tg]);
            qa[kk][1] = f2tf32(Qhi[kk*8 + tg]);
            qa[kk][2] = f2tf32(Qlo[kk*8 + tg + 4]);
            qa[kk][3] = f2tf32(Qhi[kk*8 + tg + 4]);
        }
    }

    float oacc[16][4];
    #pragma unroll
    for (int ni = 0; ni < 16; ni++)
        #pragma unroll
        for (int r = 0; r < 4; r++) oacc[ni][r] = 0.f;

    float m_lo = -1e30f, m_hi = -1e30f, l_lo = 0.f, l_hi = 0.f;
    const float scale = 0.08838834764831845f;   // 1/sqrt(128)

    // P-store column sub-positions: c0 -> ppos, c1 -> ppos+2
    const int ppos = perm8(2*tg);
    // per-warp PS rows
    const int prow_lo = (w*16 + grp) * PSS;
    const int prow_hi = prow_lo + 8*PSS;

    for (int kt = 0; kt <= qt; kt++) {
        const int k0 = kt * 64;
        __syncthreads();   // previous tile fully consumed

        // ---- load K,V tile into permuted smem ----
        #pragma unroll
        for (int i = 0; i < 16; i++) {
            const int idx  = tid + i*128;          // 0..2047
            const int quad = idx >> 2;
            const int dsub = idx & 3;
            const int key  = quad & 63;
            const int d    = ((quad >> 6) << 4) + dsub*4;
            const float4 kv = *(const float4*)(K + base + (size_t)(k0 + key)*DKH + d);
            const float4 vv = *(const float4*)(V + base + (size_t)(k0 + key)*DKH + d);
            const int pk = (key & ~7) + perm8(key & 7);
            const float ke[4] = {kv.x, kv.y, kv.z, kv.w};
            const float ve[4] = {vv.x, vv.y, vv.z, vv.w};
            #pragma unroll
            for (int c = 0; c < 4; c++) {
                const int dd = d + c;
                KS[key*KSS + (dd & ~7) + perm8(dd & 7)] = ke[c];
                VS[dd*VSS + pk] = ve[c];
            }
        }
        __syncthreads();

        // ---- S = Q K^T ----
        float sacc[8][4];
        #pragma unroll
        for (int ni = 0; ni < 8; ni++)
            #pragma unroll
            for (int r = 0; r < 4; r++) sacc[ni][r] = 0.f;

        #pragma unroll
        for (int kk = 0; kk < 16; kk++) {
            #pragma unroll
            for (int ni = 0; ni < 8; ni++) {
                const float2 bb = *(const float2*)&KS[(ni*8 + grp)*KSS + kk*8 + 2*tg];
                uint32_t bv[2] = { __float_as_uint(bb.x), __float_as_uint(bb.y) };
                mma_tf32(sacc[ni], qa[kk], bv);
            }
        }

        // ---- online softmax (fp32, in C-fragment registers) ----
        const bool diag = (kt == qt);
        float mloc_lo = -1e30f, mloc_hi = -1e30f;
        #pragma unroll
        for (int ni = 0; ni < 8; ni++) {
            const int col = k0 + ni*8 + 2*tg;
            float s0 = sacc[ni][0]*scale, s1 = sacc[ni][1]*scale;
            float s2 = sacc[ni][2]*scale, s3 = sacc[ni][3]*scale;
            if (diag) {
                if (col     > mlo    ) s0 = -1e30f;
                if (col + 1 > mlo    ) s1 = -1e30f;
                if (col     > mlo + 8) s2 = -1e30f;
                if (col + 1 > mlo + 8) s3 = -1e30f;
            }
            sacc[ni][0] = s0; sacc[ni][1] = s1; sacc[ni][2] = s2; sacc[ni][3] = s3;
            mloc_lo = fmaxf(mloc_lo, fmaxf(s0, s1));
            mloc_hi = fmaxf(mloc_hi, fmaxf(s2, s3));
        }
        mloc_lo = fmaxf(mloc_lo, __shfl_xor_sync(0xffffffffu, mloc_lo, 1));
        mloc_lo = fmaxf(mloc_lo, __shfl_xor_sync(0xffffffffu, mloc_lo, 2));
        mloc_hi = fmaxf(mloc_hi, __shfl_xor_sync(0xffffffffu, mloc_hi, 1));
        mloc_hi = fmaxf(mloc_hi, __shfl_xor_sync(0xffffffffu, mloc_hi, 2));

        const float mn_lo = fmaxf(m_lo, mloc_lo);
        const float mn_hi = fmaxf(m_hi, mloc_hi);
        const float corr_lo = __expf(m_lo - mn_lo);
        const float corr_hi = __expf(m_hi - mn_hi);

        float ls_lo = 0.f, ls_hi = 0.f;
        #pragma unroll
        for (int ni = 0; ni < 8; ni++) {
            const float p0 = __expf(sacc[ni][0] - mn_lo);
            const float p1 = __expf(sacc[ni][1] - mn_lo);
            const float p2 = __expf(sacc[ni][2] - mn_hi);
            const float p3 = __expf(sacc[ni][3] - mn_hi);
            ls_lo += p0 + p1;
            ls_hi += p2 + p3;
            const int pc = ni*8 + ppos;
            PS[prow_lo + pc]     = __uint_as_float(f2tf32(p0));
            PS[prow_lo + pc + 2] = __uint_as_float(f2tf32(p1));
            PS[prow_hi + pc]     = __uint_as_float(f2tf32(p2));
            PS[prow_hi + pc + 2] = __uint_as_float(f2tf32(p3));
        }
        l_lo = l_lo*corr_lo + ls_lo;  m_lo = mn_lo;
        l_hi = l_hi*corr_hi + ls_hi;  m_hi = mn_hi;

        #pragma unroll
        for (int ni = 0; ni < 16; ni++) {
            oacc[ni][0] *= corr_lo; oacc[ni][1] *= corr_lo;
            oacc[ni][2] *= corr_hi; oacc[ni][3] *= corr_hi;
        }
        __syncwarp();   // PS visibility within warp

        // ---- O += P V ----
        #pragma unroll
        for (int kk = 0; kk < 8; kk++) {
            const float2 plo = *(const float2*)&PS[prow_lo + kk*8 + 2*tg];
            const float2 phi = *(const float2*)&PS[prow_hi + kk*8 + 2*tg];
            uint32_t pa[4] = { __float_as_uint(plo.x), __float_as_uint(phi.x),
                               __float_as_uint(plo.y), __float_as_uint(phi.y) };
            #pragma unroll
            for (int ni = 0; ni < 16; ni++) {
                const float2 bb = *(const float2*)&VS[(ni*8 + grp)*VSS + kk*8 + 2*tg];
                uint32_t bv[2] = { __float_as_uint(bb.x), __float_as_uint(bb.y) };
                mma_tf32(oacc[ni], pa, bv);
            }
        }
    }

    // ---- epilogue: normalize and write [b][s][h*dk] ----
    l_lo += __shfl_xor_sync(0xffffffffu, l_lo, 1);
    l_lo += __shfl_xor_sync(0xffffffffu, l_lo, 2);
    l_hi += __shfl_xor_sync(0xffffffffu, l_hi, 1);
    l_hi += __shfl_xor_sync(0xffffffffu, l_hi, 2);
    const float iv_lo = 1.f / l_lo;
    const float iv_hi = 1.f / l_hi;

    float* olo = Out + ((size_t)(b*SEQ + mlo))*DMODEL + h*DKH;
    float* ohi = olo + (size_t)8*DMODEL;
    #pragma unroll
    for (int ni = 0; ni < 16; ni++) {
        *(float2*)(olo + ni*8 + 2*tg) = make_float2(oacc[ni][0]*iv_lo, oacc[ni][1]*iv_lo);
        *(float2*)(ohi + ni*8 + 2*tg) = make_float2(oacc[ni][2]*iv_hi, oacc[ni][3]*iv_hi);
    }
}

// ---------------------------------------------------------------------------
extern "C" void kernel_launch(void* const* d_in, const int* in_sizes, int n_in,
                              void* d_out, int out_size)
{
    (void)in_sizes; (void)n_in; (void)out_size;
    const float* x  = (const float*)d_in[0];
    const int*   tp = (const int*)  d_in[1];
    const float* wq = (const float*)d_in[2];
    const float* wk = (const float*)d_in[3];
    const float* wv = (const float*)d_in[4];
    const float* wo = (const float*)d_in[5];
    float* out = (float*)d_out;

    float *Qp, *Kp, *Vp, *AOp;
    cudaGetSymbolAddress((void**)&Qp,  g_Q);
    cudaGetSymbolAddress((void**)&Kp,  g_K);
    cudaGetSymbolAddress((void**)&Vp,  g_V);
    cudaGetSymbolAddress((void**)&AOp, g_AO);

    const dim3 gg(DMODEL/128, MTOT/128);
    gemm_tc<1><<<gg, 256>>>(x, wq, tp, Qp);
    gemm_tc<1><<<gg, 256>>>(x, wk, tp, Kp);
    gemm_tc<0><<<gg, 256>>>(x, wv, tp, Vp);

    const int smem = (64*KSS + 128*VSS + 64*PSS) * (int)sizeof(float);
    cudaFuncSetAttribute(attn_tc,
                         cudaFuncAttributeMaxDynamicSharedMemorySize, smem);
    attn_tc<<<dim3(SEQ/64, NHEAD, BATCH), 128, smem>>>(Qp, Kp, Vp, AOp);

    gemm_tc<2><<<gg, 256>>>(AOp, wo, tp, out);
}